// round 15
// baseline (speedup 1.0000x reference)
#include <cuda_runtime.h>
#include <cuda_bf16.h>
#include <cuda_fp16.h>
#include <cstdint>

#define NNODES 50000
#define NEDGES 600000
#define NRBF   50
#define DDIM   128
#define CUTOFF_F 5.0f
#define PI_F 3.14159265358979f
#define NBLK   196   // ceil(50000/256)

// __device__ scratch (no cudaMalloc allowed)
__device__ uint4 g_xedge[NEDGES * 16];     // 153.6 MB: x_edge*cut, fp16, SORTED rows
__device__ float g_xint[NNODES * DDIM];    // 25.6 MB segment-sum result
__device__ int   g_count[NNODES];
__device__ int   g_cursor[NNODES];
__device__ int   g_offset[NNODES + 1];
__device__ int   g_pos[NEDGES];            // e -> sorted position
__device__ int   g_snt[NEDGES];            // node_type[src] in sorted order
__device__ int   g_bsum[256];
__device__ int   g_bpre[256];

// ---------------------------------------------------------------------------
__device__ __forceinline__ uint32_t smem_u32(const void* p) {
    uint32_t a;
    asm("{ .reg .u64 t; cvta.to.shared.u64 t, %1; cvt.u32.u64 %0, t; }"
        : "=r"(a) : "l"(p));
    return a;
}
__device__ __forceinline__ uint32_t swz128(uint32_t o) { return o ^ ((o >> 3) & 0x70); }

__device__ __forceinline__ void ldmatrix4(uint32_t r[4], uint32_t addr) {
    asm volatile("ldmatrix.sync.aligned.m8n8.x4.shared.b16 {%0,%1,%2,%3}, [%4];"
                 : "=r"(r[0]), "=r"(r[1]), "=r"(r[2]), "=r"(r[3]) : "r"(addr));
}
__device__ __forceinline__ void mma_bf16(float d[4], const uint32_t a[4],
                                         const uint32_t b[2]) {
    asm volatile("mma.sync.aligned.m16n8k16.row.col.f32.bf16.bf16.f32 "
                 "{%0,%1,%2,%3}, {%4,%5,%6,%7}, {%8,%9}, {%0,%1,%2,%3};"
                 : "+f"(d[0]), "+f"(d[1]), "+f"(d[2]), "+f"(d[3])
                 : "r"(a[0]), "r"(a[1]), "r"(a[2]), "r"(a[3]),
                   "r"(b[0]), "r"(b[1]));
}
__device__ __forceinline__ void mma_tf32(float d[4], const uint32_t a[4],
                                         const uint32_t b[2]) {
    asm volatile("mma.sync.aligned.m16n8k8.row.col.f32.tf32.tf32.f32 "
                 "{%0,%1,%2,%3}, {%4,%5,%6,%7}, {%8,%9}, {%0,%1,%2,%3};"
                 : "+f"(d[0]), "+f"(d[1]), "+f"(d[2]), "+f"(d[3])
                 : "r"(a[0]), "r"(a[1]), "r"(a[2]), "r"(a[3]),
                   "r"(b[0]), "r"(b[1]));
}
__device__ __forceinline__ uint32_t pack_bf2(float x, float y) {
    __nv_bfloat162 h = __floats2bfloat162_rn(x, y);
    return *reinterpret_cast<uint32_t*>(&h);
}
__device__ __forceinline__ uint32_t pack_h2(float x, float y) {
    __half2 h = __floats2half2_rn(x, y);
    return *reinterpret_cast<uint32_t*>(&h);
}
__device__ __forceinline__ float to_tf32(float x) {
    float r;
    asm("cvt.rna.tf32.f32 %0, %1;" : "=f"(r) : "f"(x));
    return r;
}

// ---------------------------------------------------------------------------
// Zero g_count + sentinel offset
// ---------------------------------------------------------------------------
__global__ void zero_kernel() {
    int i = blockIdx.x * blockDim.x + threadIdx.x;
    if (i < NNODES) g_count[i] = 0;
    if (i == 0) g_offset[NNODES] = NEDGES;
}

// ---------------------------------------------------------------------------
// Sort chain: histogram -> 3-step exclusive scan -> scatter pos/snt
// ---------------------------------------------------------------------------
__global__ void hist_kernel(const int* __restrict__ dst) {
    int e = blockIdx.x * blockDim.x + threadIdx.x;
    if (e < NEDGES) atomicAdd(&g_count[dst[e]], 1);
}

__global__ void scan_s1() {
    __shared__ int sd[256];
    const int b = blockIdx.x, t = threadIdx.x;
    const int i = b * 256 + t;
    sd[t] = (i < NNODES) ? g_count[i] : 0;
    __syncthreads();
    for (int s = 128; s > 0; s >>= 1) {
        if (t < s) sd[t] += sd[t + s];
        __syncthreads();
    }
    if (t == 0) g_bsum[b] = sd[0];
}

__global__ void scan_s2() {
    __shared__ int sc[256];
    const int t = threadIdx.x;
    sc[t] = (t < NBLK) ? g_bsum[t] : 0;
    __syncthreads();
    for (int off = 1; off < 256; off <<= 1) {
        int y = (t >= off) ? sc[t - off] : 0;
        __syncthreads();
        sc[t] += y;
        __syncthreads();
    }
    if (t < NBLK) g_bpre[t] = (t == 0) ? 0 : sc[t - 1];
}

__global__ void scan_s3() {
    __shared__ int sc[256];
    const int b = blockIdx.x, t = threadIdx.x;
    const int i = b * 256 + t;
    const int v = (i < NNODES) ? g_count[i] : 0;
    sc[t] = v;
    __syncthreads();
    for (int off = 1; off < 256; off <<= 1) {
        int y = (t >= off) ? sc[t - off] : 0;
        __syncthreads();
        sc[t] += y;
        __syncthreads();
    }
    if (i < NNODES) {
        const int excl = g_bpre[b] + sc[t] - v;
        g_offset[i] = excl;
        g_cursor[i] = excl;
    }
}

__global__ void scatter_sort_kernel(const int* __restrict__ dst,
                                    const int* __restrict__ src,
                                    const int* __restrict__ node_type) {
    int e = blockIdx.x * blockDim.x + threadIdx.x;
    if (e < NEDGES) {
        const int idx = atomicAdd(&g_cursor[dst[e]], 1);
        g_pos[e] = idx;
        g_snt[idx] = node_type[src[e]];
    }
}

// ---------------------------------------------------------------------------
// Edge GEMM (tf32 single-pass, natural edge order -> sequential rbf reads):
//   x_edge = (rbf @ W_e^T + b_e) * cut, stored fp16 to SORTED row g_pos[e].
// A layout per k-chunk of 8 cols: row stride 32B, col k at byte
// (k&3)*8 + (k>>2)*4. K padded 56: cols 0..49 rbf, 50 = 1.0 (bias).
// ---------------------------------------------------------------------------
#define TILE_E 128
#define NKS    7
#define CHUNK_B 4096                     // 128 rows * 32 bytes
#define MSGU   68                        // uint32 stride per msg row (conflict-free)
#define A_OFF    0
#define MSG_OFF  (NKS * CHUNK_B)                      // 28672
#define POS_OFF  (MSG_OFF + TILE_E * MSGU * 4)        // 63488
#define CUT_OFF  (POS_OFF + 512)
#define EDGE_SMEM (CUT_OFF + 512)                     // 64512

__device__ __forceinline__ float we_elem(const float* W_e, const float* b_e,
                                         int d, int k) {
    if (k < NRBF) return W_e[d * NRBF + k];
    if (k == NRBF) return b_e[d];
    return 0.f;
}
__device__ __forceinline__ uint32_t kbyte(int k) {
    return (uint32_t)((k & 3) * 8 + ((k >> 2) & 1) * 4);
}

__global__ __launch_bounds__(256) void edge_gemm_kernel(
    const float* __restrict__ rbf,
    const float* __restrict__ dist,
    const float* __restrict__ W_e,
    const float* __restrict__ b_e)
{
    extern __shared__ __align__(1024) char smem[];
    const int t    = threadIdx.x;
    const int lane = t & 31;
    const int wid  = t >> 5;

    uint32_t* msg_s = reinterpret_cast<uint32_t*>(smem + MSG_OFF);
    int*      pos_s = reinterpret_cast<int*>(smem + POS_OFF);
    float*    cut_s = reinterpret_cast<float*>(smem + CUT_OFF);

    // B = W_e tf32 fragments in registers
    uint32_t Bt[2][NKS][2];
#pragma unroll
    for (int n2 = 0; n2 < 2; ++n2) {
        const int d = wid * 16 + n2 * 8 + (lane >> 2);
#pragma unroll
        for (int ks = 0; ks < NKS; ++ks) {
            const int k = ks * 8 + (lane & 3);
            Bt[n2][ks][0] = __float_as_uint(to_tf32(we_elem(W_e, b_e, d, k)));
            Bt[n2][ks][1] = __float_as_uint(to_tf32(we_elem(W_e, b_e, d, k + 4)));
        }
    }

    const int tile = blockIdx.x;
    const int i0 = tile * TILE_E;

    // ---- stage pos + cut (sequential) ----
    if (t < TILE_E) {
        const int e = i0 + t;
        int p = -1;
        float cut = 0.f;
        if (e < NEDGES) {
            p = g_pos[e];
            const float dis = dist[e];
            if (dis < CUTOFF_F)
                cut = 0.5f * (__cosf(dis * (PI_F / CUTOFF_F)) + 1.0f);
        }
        pos_s[t] = p; cut_s[t] = cut;
    }
    __syncthreads();

    // ---- stage A tile: 128 rows x 28 col-pairs, SEQUENTIAL rbf reads ----
    for (int idx = t; idx < TILE_E * 28; idx += 256) {
        const int row = idx / 28, p = idx - row * 28;
        const int k0 = 2 * p;
        float vx = 0.f, vy = 0.f;
        if (p < 25) {
            const int e = i0 + row;
            if (e < NEDGES) {
                const float2 v =
                    reinterpret_cast<const float2*>(rbf + (size_t)e * NRBF)[p];
                vx = to_tf32(v.x); vy = to_tf32(v.y);
            }
        } else if (p == 25) {
            vx = 1.0f;  // bias column 50
        }
        char* base = smem + A_OFF + (k0 >> 3) * CHUNK_B + row * 32;
        *reinterpret_cast<float*>(base + kbyte(k0))     = vx;
        *reinterpret_cast<float*>(base + kbyte(k0 + 1)) = vy;
    }
    __syncthreads();

    // ---- MMA: 8 m-blocks of 16 edges, single tf32 pass ----
    const int rfrag = lane >> 2;
    const int kq    = lane & 3;
#pragma unroll 1
    for (int mb = 0; mb < 8; ++mb) {
        const int r0 = mb * 16 + rfrag;
        float D[2][4] = {{0.f, 0.f, 0.f, 0.f}, {0.f, 0.f, 0.f, 0.f}};
#pragma unroll
        for (int ks = 0; ks < NKS; ++ks) {
            const char* ch = smem + A_OFF + ks * CHUNK_B;
            const float2 lo = *reinterpret_cast<const float2*>(ch + r0 * 32 + kq * 8);
            const float2 hi = *reinterpret_cast<const float2*>(ch + (r0 + 8) * 32 + kq * 8);
            uint32_t A[4];
            A[0] = __float_as_uint(lo.x);
            A[1] = __float_as_uint(hi.x);
            A[2] = __float_as_uint(lo.y);
            A[3] = __float_as_uint(hi.y);
            mma_tf32(D[0], A, Bt[0][ks]);
            mma_tf32(D[1], A, Bt[1][ks]);
        }
        // write fp16 pairs to msg smem (stride 68 uint32 -> conflict-free)
        const int g = lane >> 2, tq = lane & 3;
        const int rr = mb * 16 + g;
        const float c0 = cut_s[rr], c8 = cut_s[rr + 8];
#pragma unroll
        for (int n2 = 0; n2 < 2; ++n2) {
            const int cu = wid * 8 + n2 * 4 + tq;   // uint32 (=half2) column index
            msg_s[rr * MSGU + cu]       = pack_h2(D[n2][0] * c0, D[n2][1] * c0);
            msg_s[(rr + 8) * MSGU + cu] = pack_h2(D[n2][2] * c8, D[n2][3] * c8);
        }
    }
    __syncthreads();

    // ---- scatter rows to sorted positions (256B fp16 rows, 16 uint4 each) ----
    for (int q = t; q < TILE_E * 16; q += 256) {
        const int j = q >> 4, c = q & 15;
        const int p = pos_s[j];
        if (p >= 0) {
            const uint4 v = *reinterpret_cast<const uint4*>(msg_s + j * MSGU + c * 4);
            g_xedge[(size_t)p * 16 + c] = v;
        }
    }
}

// ---------------------------------------------------------------------------
// Gather (sequential, atomic-free): warp per node,
//   x_int[n] = sum_{j in [offset[n],offset[n+1])} x_edge_sorted[j] * emb[snt[j]]
// ---------------------------------------------------------------------------
__global__ __launch_bounds__(256) void gather_kernel(const float* __restrict__ emb) {
    const int lane = threadIdx.x & 31;
    const int w    = threadIdx.x >> 5;
    const int n = blockIdx.x * 8 + w;
    if (n >= NNODES) return;

    const int beg = g_offset[n], end = g_offset[n + 1];
    const uint2* xe2 = reinterpret_cast<const uint2*>(g_xedge);
    const float4* emb4 = reinterpret_cast<const float4*>(emb);

    float4 acc = make_float4(0.f, 0.f, 0.f, 0.f);
    for (int j = beg; j < end; ++j) {
        const uint2 h = xe2[(size_t)j * 32 + lane];       // 4 fp16 dims
        const int nt = g_snt[j];                          // broadcast
        const float4 ev = emb4[(size_t)nt * 32 + lane];   // L1-resident
        const float2 a = __half22float2(*reinterpret_cast<const __half2*>(&h.x));
        const float2 b = __half22float2(*reinterpret_cast<const __half2*>(&h.y));
        acc.x += a.x * ev.x;
        acc.y += a.y * ev.y;
        acc.z += b.x * ev.z;
        acc.w += b.y * ev.w;
    }
    reinterpret_cast<float4*>(g_xint)[(size_t)n * 32 + lane] = acc;
}

// ---------------------------------------------------------------------------
// Combine via mma.sync bf16 3-pass (proven): out[64n x 128d] tile =
//   concat(x_nodes, x_int)[64 x 256] @ W_c^T + b_c.
// ---------------------------------------------------------------------------
#define CNB 64
#define CCHUNK_B 8192
#define CA_HI 0
#define CA_LO 32768
#define COMBINE_SMEM 65536

__global__ __launch_bounds__(256, 1) void combine_mma_kernel(
    const float* __restrict__ x_nodes,
    const float* __restrict__ W_c,
    const float* __restrict__ b_c,
    float* __restrict__ out)
{
    extern __shared__ __align__(1024) char smem[];
    const uint32_t sb = smem_u32(smem);
    const int t    = threadIdx.x;
    const int lane = t & 31;
    const int wid  = t >> 5;

    uint32_t Bh[2][16][2], Bl[2][16][2];
#pragma unroll
    for (int n2 = 0; n2 < 2; ++n2) {
        const int d = wid * 16 + n2 * 8 + (lane >> 2);
#pragma unroll
        for (int ks = 0; ks < 16; ++ks) {
            const int k0 = ks * 16 + (lane & 3) * 2;
            float v[4];
            v[0] = W_c[d * 256 + k0];
            v[1] = W_c[d * 256 + k0 + 1];
            v[2] = W_c[d * 256 + k0 + 8];
            v[3] = W_c[d * 256 + k0 + 9];
            float h[4];
#pragma unroll
            for (int i = 0; i < 4; ++i)
                h[i] = __bfloat162float(__float2bfloat16_rn(v[i]));
            Bh[n2][ks][0] = pack_bf2(h[0], h[1]);
            Bh[n2][ks][1] = pack_bf2(h[2], h[3]);
            Bl[n2][ks][0] = pack_bf2(v[0] - h[0], v[1] - h[1]);
            Bl[n2][ks][1] = pack_bf2(v[2] - h[2], v[3] - h[3]);
        }
    }
    float2 bias[2];
#pragma unroll
    for (int n2 = 0; n2 < 2; ++n2) {
        const int col = wid * 16 + n2 * 8 + (lane & 3) * 2;
        bias[n2] = make_float2(b_c[col], b_c[col + 1]);
    }

    const float2* xn2 = reinterpret_cast<const float2*>(x_nodes);
    const float2* xi2 = reinterpret_cast<const float2*>(g_xint);
    const int ntiles = (NNODES + CNB - 1) / CNB;

    for (int tile = blockIdx.x; tile < ntiles; tile += gridDim.x) {
        const int n0 = tile * CNB;

        for (int idx = t; idx < CNB * 128; idx += 256) {
            const int row = idx >> 7, p = idx & 127;
            const int n = n0 + row;
            float2 v = make_float2(0.f, 0.f);
            if (n < NNODES)
                v = (p < 64) ? xn2[(size_t)n * 64 + p]
                             : xi2[(size_t)n * 64 + (p - 64)];
            const float hx = __bfloat162float(__float2bfloat16_rn(v.x));
            const float hy = __bfloat162float(__float2bfloat16_rn(v.y));
            const uint32_t off = (uint32_t)(p >> 5) * CCHUNK_B +
                swz128((uint32_t)(row * 128 + (p & 31) * 4));
            *reinterpret_cast<uint32_t*>(smem + CA_HI + off) = pack_bf2(hx, hy);
            *reinterpret_cast<uint32_t*>(smem + CA_LO + off) =
                pack_bf2(v.x - hx, v.y - hy);
        }
        __syncthreads();

        const int rowm = lane & 15;
        const int khb  = (lane >> 4) ? 16 : 0;
#pragma unroll 1
        for (int mb = 0; mb < 4; ++mb) {
            float D[2][4] = {{0.f, 0.f, 0.f, 0.f}, {0.f, 0.f, 0.f, 0.f}};
            const uint32_t rowbase = (uint32_t)((mb * 16 + rowm) * 128) + khb;
#pragma unroll
            for (int ks = 0; ks < 16; ++ks) {
                const uint32_t off = (uint32_t)(ks >> 2) * CCHUNK_B +
                    swz128(rowbase + (ks & 3) * 32);
                uint32_t Ah[4], Al[4];
                ldmatrix4(Ah, sb + CA_HI + off);
                ldmatrix4(Al, sb + CA_LO + off);
#pragma unroll
                for (int n2 = 0; n2 < 2; ++n2) {
                    mma_bf16(D[n2], Ah, Bh[n2][ks]);
                    mma_bf16(D[n2], Ah, Bl[n2][ks]);
                    mma_bf16(D[n2], Al, Bh[n2][ks]);
                }
            }
            const int g = lane >> 2, tq = lane & 3;
            const int r0 = n0 + mb * 16 + g;
#pragma unroll
            for (int n2 = 0; n2 < 2; ++n2) {
                const int col = wid * 16 + n2 * 8 + tq * 2;
                if (r0 < NNODES)
                    *reinterpret_cast<float2*>(out + (size_t)r0 * DDIM + col) =
                        make_float2(D[n2][0] + bias[n2].x, D[n2][1] + bias[n2].y);
                if (r0 + 8 < NNODES)
                    *reinterpret_cast<float2*>(out + (size_t)(r0 + 8) * DDIM + col) =
                        make_float2(D[n2][2] + bias[n2].x, D[n2][3] + bias[n2].y);
            }
        }
        __syncthreads();
    }
}

// ---------------------------------------------------------------------------
// Launch. Inputs (metadata order):
//  0 node_type(i32)  1 x_nodes(f32)  2 src(i32)  3 dst(i32)  4 rbf_edges(f32)
//  5 dist(f32)       6 emb(f32)      7 W_e(f32)  8 b_e(f32)  9 W_c(f32) 10 b_c(f32)
// ---------------------------------------------------------------------------
extern "C" void kernel_launch(void* const* d_in, const int* in_sizes, int n_in,
                              void* d_out, int out_size) {
    const int*   node_type = (const int*)  d_in[0];
    const float* x_nodes   = (const float*)d_in[1];
    const int*   src       = (const int*)  d_in[2];
    const int*   dst       = (const int*)  d_in[3];
    const float* rbf       = (const float*)d_in[4];
    const float* dist      = (const float*)d_in[5];
    const float* emb       = (const float*)d_in[6];
    const float* W_e       = (const float*)d_in[7];
    const float* b_e       = (const float*)d_in[8];
    const float* W_c       = (const float*)d_in[9];
    const float* b_c       = (const float*)d_in[10];
    float* out = (float*)d_out;

    int sms = 148;
    cudaDeviceGetAttribute(&sms, cudaDevAttrMultiProcessorCount, 0);

    cudaFuncSetAttribute(edge_gemm_kernel,
                         cudaFuncAttributeMaxDynamicSharedMemorySize, EDGE_SMEM);
    cudaFuncSetAttribute(combine_mma_kernel,
                         cudaFuncAttributeMaxDynamicSharedMemorySize, COMBINE_SMEM);

    const int eb = (NEDGES + 511) / 512;          // 1172
    const int ntiles = (NEDGES + TILE_E - 1) / TILE_E;  // 4688

    zero_kernel<<<(NNODES + 511) / 512, 512>>>();
    hist_kernel<<<eb, 512>>>(dst);
    scan_s1<<<NBLK, 256>>>();
    scan_s2<<<1, 256>>>();
    scan_s3<<<NBLK, 256>>>();
    scatter_sort_kernel<<<eb, 512>>>(dst, src, node_type);
    edge_gemm_kernel<<<ntiles, 256, EDGE_SMEM>>>(rbf, dist, W_e, b_e);
    gather_kernel<<<(NNODES + 7) / 8, 256>>>(emb);
    combine_mma_kernel<<<sms, 256, COMBINE_SMEM>>>(x_nodes, W_c, b_c, out);
}

// round 16
// speedup vs baseline: 1.3709x; 1.3709x over previous
#include <cuda_runtime.h>
#include <cuda_bf16.h>
#include <cuda_fp16.h>
#include <cstdint>

#define NNODES 50000
#define NEDGES 600000
#define NRBF   50
#define DDIM   128
#define CUTOFF_F 5.0f
#define PI_F 3.14159265358979f
#define NBLK   196   // ceil(50000/256)

// __device__ scratch (no cudaMalloc allowed)
__device__ float g_xint[NNODES * DDIM];    // 25.6 MB segment-sum result
__device__ int   g_count[NNODES];
__device__ int   g_cursor[NNODES];
__device__ int4  g_sedge[NEDGES];          // sorted-by-dst: {eid, dst, nt, cut_bits}
__device__ int   g_bsum[256];
__device__ int   g_bpre[256];

// ---------------------------------------------------------------------------
__device__ __forceinline__ uint32_t smem_u32(const void* p) {
    uint32_t a;
    asm("{ .reg .u64 t; cvta.to.shared.u64 t, %1; cvt.u32.u64 %0, t; }"
        : "=r"(a) : "l"(p));
    return a;
}
__device__ __forceinline__ uint32_t swz128(uint32_t o) { return o ^ ((o >> 3) & 0x70); }

__device__ __forceinline__ void ldmatrix4(uint32_t r[4], uint32_t addr) {
    asm volatile("ldmatrix.sync.aligned.m8n8.x4.shared.b16 {%0,%1,%2,%3}, [%4];"
                 : "=r"(r[0]), "=r"(r[1]), "=r"(r[2]), "=r"(r[3]) : "r"(addr));
}
__device__ __forceinline__ void mma_bf16(float d[4], const uint32_t a[4],
                                         const uint32_t b[2]) {
    asm volatile("mma.sync.aligned.m16n8k16.row.col.f32.bf16.bf16.f32 "
                 "{%0,%1,%2,%3}, {%4,%5,%6,%7}, {%8,%9}, {%0,%1,%2,%3};"
                 : "+f"(d[0]), "+f"(d[1]), "+f"(d[2]), "+f"(d[3])
                 : "r"(a[0]), "r"(a[1]), "r"(a[2]), "r"(a[3]),
                   "r"(b[0]), "r"(b[1]));
}
__device__ __forceinline__ void mma_tf32(float d[4], const uint32_t a[4],
                                         const uint32_t b[2]) {
    asm volatile("mma.sync.aligned.m16n8k8.row.col.f32.tf32.tf32.f32 "
                 "{%0,%1,%2,%3}, {%4,%5,%6,%7}, {%8,%9}, {%0,%1,%2,%3};"
                 : "+f"(d[0]), "+f"(d[1]), "+f"(d[2]), "+f"(d[3])
                 : "r"(a[0]), "r"(a[1]), "r"(a[2]), "r"(a[3]),
                   "r"(b[0]), "r"(b[1]));
}
__device__ __forceinline__ uint32_t pack_bf2(float x, float y) {
    __nv_bfloat162 h = __floats2bfloat162_rn(x, y);
    return *reinterpret_cast<uint32_t*>(&h);
}
__device__ __forceinline__ uint32_t pack_h2(float x, float y) {
    __half2 h = __floats2half2_rn(x, y);
    return *reinterpret_cast<uint32_t*>(&h);
}
__device__ __forceinline__ float to_tf32(float x) {
    float r;
    asm("cvt.rna.tf32.f32 %0, %1;" : "=f"(r) : "f"(x));
    return r;
}

// ---------------------------------------------------------------------------
// Zero scratch: g_xint + g_count
// ---------------------------------------------------------------------------
__global__ void zero_kernel() {
    int i = blockIdx.x * blockDim.x + threadIdx.x;
    const int n4 = NNODES * DDIM / 4;
    float4* p = reinterpret_cast<float4*>(g_xint);
    float4 z = make_float4(0.f, 0.f, 0.f, 0.f);
    for (int j = i; j < n4; j += gridDim.x * blockDim.x) p[j] = z;
    for (int j = i; j < NNODES; j += gridDim.x * blockDim.x) g_count[j] = 0;
}

// ---------------------------------------------------------------------------
// Sort chain: histogram -> 3-step exclusive scan -> scatter sorted records
// ---------------------------------------------------------------------------
__global__ void hist_kernel(const int* __restrict__ dst) {
    int e = blockIdx.x * blockDim.x + threadIdx.x;
    if (e < NEDGES) atomicAdd(&g_count[dst[e]], 1);
}

__global__ void scan_s1() {
    __shared__ int sd[256];
    const int b = blockIdx.x, t = threadIdx.x;
    const int i = b * 256 + t;
    sd[t] = (i < NNODES) ? g_count[i] : 0;
    __syncthreads();
    for (int s = 128; s > 0; s >>= 1) {
        if (t < s) sd[t] += sd[t + s];
        __syncthreads();
    }
    if (t == 0) g_bsum[b] = sd[0];
}

__global__ void scan_s2() {
    __shared__ int sc[256];
    const int t = threadIdx.x;
    sc[t] = (t < NBLK) ? g_bsum[t] : 0;
    __syncthreads();
    for (int off = 1; off < 256; off <<= 1) {
        int y = (t >= off) ? sc[t - off] : 0;
        __syncthreads();
        sc[t] += y;
        __syncthreads();
    }
    if (t < NBLK) g_bpre[t] = (t == 0) ? 0 : sc[t - 1];
}

__global__ void scan_s3() {
    __shared__ int sc[256];
    const int b = blockIdx.x, t = threadIdx.x;
    const int i = b * 256 + t;
    const int v = (i < NNODES) ? g_count[i] : 0;
    sc[t] = v;
    __syncthreads();
    for (int off = 1; off < 256; off <<= 1) {
        int y = (t >= off) ? sc[t - off] : 0;
        __syncthreads();
        sc[t] += y;
        __syncthreads();
    }
    if (i < NNODES) g_cursor[i] = g_bpre[b] + sc[t] - v;
}

__global__ void scatter_sort_kernel(const int* __restrict__ dst,
                                    const int* __restrict__ src,
                                    const int* __restrict__ node_type,
                                    const float* __restrict__ dist) {
    int e = blockIdx.x * blockDim.x + threadIdx.x;
    if (e < NEDGES) {
        const int d = dst[e];
        const float dis = dist[e];           // sequential read here
        float cut = 0.f;
        if (dis < CUTOFF_F)
            cut = 0.5f * (__cosf(dis * (PI_F / CUTOFF_F)) + 1.0f);
        const int idx = atomicAdd(&g_cursor[d], 1);
        g_sedge[idx] = make_int4(e, d, node_type[src[e]], __float_as_int(cut));
    }
}

// ---------------------------------------------------------------------------
// Fused edge kernel: tf32 single-pass GEMM over sorted edges + segmented
// reduction + per-segment red.global.add.v4. msg in fp16 smem.
// A layout per k-chunk of 8 cols: row stride 32B, col k at byte
// (k&3)*8 + (k>>2)*4. K padded 56: cols 0..49 rbf, 50 = 1.0 (bias).
// ~66 KB smem -> 3 CTAs/SM.
// ---------------------------------------------------------------------------
#define TILE_E 128
#define NKS    7
#define CHUNK_B 4096                     // 128 rows * 32 bytes
#define MSGU   68                        // uint32 stride per msg row (conflict-free)
#define A_OFF    0
#define MSG_OFF  (NKS * CHUNK_B)                      // 28672
#define CUT_OFF  (MSG_OFF + TILE_E * MSGU * 4)        // 63488
#define DST_OFF  (CUT_OFF + 512)
#define NTS_OFF  (DST_OFF + 512)
#define EID_OFF  (NTS_OFF + 512)
#define SEG_OFF  (EID_OFF + 512)
#define WTOT_OFF (SEG_OFF + 512)
#define EDGE_SMEM (WTOT_OFF + 64)                     // 66112

__device__ __forceinline__ float we_elem(const float* W_e, const float* b_e,
                                         int d, int k) {
    if (k < NRBF) return W_e[d * NRBF + k];
    if (k == NRBF) return b_e[d];
    return 0.f;
}
__device__ __forceinline__ uint32_t kbyte(int k) {
    return (uint32_t)((k & 3) * 8 + ((k >> 2) & 1) * 4);
}

__global__ __launch_bounds__(256, 3) void fused_edge_kernel(
    const float* __restrict__ rbf,
    const float* __restrict__ emb,
    const float* __restrict__ W_e,
    const float* __restrict__ b_e)
{
    extern __shared__ __align__(1024) char smem[];
    const int t    = threadIdx.x;
    const int lane = t & 31;
    const int wid  = t >> 5;

    uint32_t* msg_s = reinterpret_cast<uint32_t*>(smem + MSG_OFF);
    float*    cut_s = reinterpret_cast<float*>(smem + CUT_OFF);
    int*      dst_s = reinterpret_cast<int*>(smem + DST_OFF);
    int*      nts_s = reinterpret_cast<int*>(smem + NTS_OFF);
    int*      eid_s = reinterpret_cast<int*>(smem + EID_OFF);
    int*      seg_s = reinterpret_cast<int*>(smem + SEG_OFF);
    int*      wtot_s = reinterpret_cast<int*>(smem + WTOT_OFF);

    // B = W_e tf32 fragments in registers
    uint32_t Bt[2][NKS][2];
#pragma unroll
    for (int n2 = 0; n2 < 2; ++n2) {
        const int d = wid * 16 + n2 * 8 + (lane >> 2);
#pragma unroll
        for (int ks = 0; ks < NKS; ++ks) {
            const int k = ks * 8 + (lane & 3);
            Bt[n2][ks][0] = __float_as_uint(to_tf32(we_elem(W_e, b_e, d, k)));
            Bt[n2][ks][1] = __float_as_uint(to_tf32(we_elem(W_e, b_e, d, k + 4)));
        }
    }
    __syncthreads();

    const int ntiles = (NEDGES + TILE_E - 1) / TILE_E;  // 4688
    const float4* emb4 = reinterpret_cast<const float4*>(emb);

    for (int tile = blockIdx.x; tile < ntiles; tile += gridDim.x) {
        const int i0 = tile * TILE_E;

        // ---- stage sorted records (cut precomputed) ----
        if (t < TILE_E) {
            const int i = i0 + t;
            int e = -1, d = -1, nt = 0;
            float cut = 0.f;
            if (i < NEDGES) {
                const int4 v = g_sedge[i];
                e = v.x; d = v.y; nt = v.z; cut = __int_as_float(v.w);
            }
            eid_s[t] = e; dst_s[t] = d; nts_s[t] = nt; cut_s[t] = cut;
        }
        __syncthreads();

        // ---- stage A tile: gathered rbf rows, tf32-rounded ----
        for (int idx = t; idx < TILE_E * 28; idx += 256) {
            const int row = idx / 28, p = idx - row * 28;
            const int k0 = 2 * p;
            float vx = 0.f, vy = 0.f;
            if (p < 25) {
                const int e = eid_s[row];
                if (e >= 0) {
                    const float2 v =
                        reinterpret_cast<const float2*>(rbf + (size_t)e * NRBF)[p];
                    vx = to_tf32(v.x); vy = to_tf32(v.y);
                }
            } else if (p == 25) {
                vx = 1.0f;  // bias column 50
            }
            char* base = smem + A_OFF + (k0 >> 3) * CHUNK_B + row * 32;
            *reinterpret_cast<float*>(base + kbyte(k0))     = vx;
            *reinterpret_cast<float*>(base + kbyte(k0 + 1)) = vy;
        }
        __syncthreads();

        // ---- MMA: 8 m-blocks of 16 edges, single tf32 pass ----
        const int rfrag = lane >> 2;
        const int kq    = lane & 3;
#pragma unroll 1
        for (int mb = 0; mb < 8; ++mb) {
            const int r0 = mb * 16 + rfrag;
            float D[2][4] = {{0.f, 0.f, 0.f, 0.f}, {0.f, 0.f, 0.f, 0.f}};
#pragma unroll
            for (int ks = 0; ks < NKS; ++ks) {
                const char* ch = smem + A_OFF + ks * CHUNK_B;
                const float2 lo = *reinterpret_cast<const float2*>(ch + r0 * 32 + kq * 8);
                const float2 hi = *reinterpret_cast<const float2*>(ch + (r0 + 8) * 32 + kq * 8);
                uint32_t A[4];
                A[0] = __float_as_uint(lo.x);
                A[1] = __float_as_uint(hi.x);
                A[2] = __float_as_uint(lo.y);
                A[3] = __float_as_uint(hi.y);
                mma_tf32(D[0], A, Bt[0][ks]);
                mma_tf32(D[1], A, Bt[1][ks]);
            }
            // fp16 msg write (stride 68 uint32: banks 4g+tq -> conflict-free)
            const int g = lane >> 2, tq = lane & 3;
            const int rr = mb * 16 + g;
            const float c0 = cut_s[rr], c8 = cut_s[rr + 8];
#pragma unroll
            for (int n2 = 0; n2 < 2; ++n2) {
                const int cu = wid * 8 + n2 * 4 + tq;   // half2 column index
                msg_s[rr * MSGU + cu]       = pack_h2(D[n2][0] * c0, D[n2][1] * c0);
                msg_s[(rr + 8) * MSGU + cu] = pack_h2(D[n2][2] * c8, D[n2][3] * c8);
            }
        }

        // ---- build segments of equal dst (ballot scan over 128 rows) ----
        int flag = 0;
        if (t < TILE_E)
            flag = (t == 0) || (dst_s[t] != dst_s[t - 1]);
        const unsigned bits = __ballot_sync(0xffffffffu, flag);
        if (t < TILE_E && lane == 0) wtot_s[wid] = __popc(bits);
        __syncthreads();
        if (t < TILE_E) {
            int base = 0;
#pragma unroll
            for (int w = 0; w < 4; ++w) base += (w < wid) ? wtot_s[w] : 0;
            if (flag) {
                const unsigned le = (lane == 31) ? 0xffffffffu
                                                 : ((1u << (lane + 1)) - 1u);
                seg_s[base + __popc(bits & le) - 1] = t;
            }
        }
        __syncthreads();
        const int nseg = wtot_s[0] + wtot_s[1] + wtot_s[2] + wtot_s[3];

        // ---- segmented sum (fp16 msg) + one red.v4 per segment per lane ----
        for (int s = wid; s < nseg; s += 8) {
            const int a = seg_s[s];
            const int b = (s + 1 < nseg) ? seg_s[s + 1] : TILE_E;
            const int dv = dst_s[a];
            if (dv < 0) continue;
            float4 acc = make_float4(0.f, 0.f, 0.f, 0.f);
            for (int j = a; j < b; ++j) {
                const uint2 h = *reinterpret_cast<const uint2*>(
                    msg_s + j * MSGU + lane * 2);
                const float2 m0 = __half22float2(*reinterpret_cast<const __half2*>(&h.x));
                const float2 m1 = __half22float2(*reinterpret_cast<const __half2*>(&h.y));
                const float4 ev = emb4[(size_t)nts_s[j] * 32 + lane];
                acc.x += m0.x * ev.x;
                acc.y += m0.y * ev.y;
                acc.z += m1.x * ev.z;
                acc.w += m1.y * ev.w;
            }
            float* p = g_xint + (size_t)dv * DDIM + lane * 4;
            asm volatile("red.global.add.v4.f32 [%0], {%1, %2, %3, %4};"
                         :: "l"(p), "f"(acc.x), "f"(acc.y),
                            "f"(acc.z), "f"(acc.w) : "memory");
        }
        __syncthreads();
    }
}

// ---------------------------------------------------------------------------
// Combine via mma.sync bf16 3-pass (proven): out[64n x 128d] tile =
//   concat(x_nodes, x_int)[64 x 256] @ W_c^T + b_c.
// ---------------------------------------------------------------------------
#define CNB 64
#define CCHUNK_B 8192
#define CA_HI 0
#define CA_LO 32768
#define COMBINE_SMEM 65536

__global__ __launch_bounds__(256, 1) void combine_mma_kernel(
    const float* __restrict__ x_nodes,
    const float* __restrict__ W_c,
    const float* __restrict__ b_c,
    float* __restrict__ out)
{
    extern __shared__ __align__(1024) char smem[];
    const uint32_t sb = smem_u32(smem);
    const int t    = threadIdx.x;
    const int lane = t & 31;
    const int wid  = t >> 5;

    uint32_t Bh[2][16][2], Bl[2][16][2];
#pragma unroll
    for (int n2 = 0; n2 < 2; ++n2) {
        const int d = wid * 16 + n2 * 8 + (lane >> 2);
#pragma unroll
        for (int ks = 0; ks < 16; ++ks) {
            const int k0 = ks * 16 + (lane & 3) * 2;
            float v[4];
            v[0] = W_c[d * 256 + k0];
            v[1] = W_c[d * 256 + k0 + 1];
            v[2] = W_c[d * 256 + k0 + 8];
            v[3] = W_c[d * 256 + k0 + 9];
            float h[4];
#pragma unroll
            for (int i = 0; i < 4; ++i)
                h[i] = __bfloat162float(__float2bfloat16_rn(v[i]));
            Bh[n2][ks][0] = pack_bf2(h[0], h[1]);
            Bh[n2][ks][1] = pack_bf2(h[2], h[3]);
            Bl[n2][ks][0] = pack_bf2(v[0] - h[0], v[1] - h[1]);
            Bl[n2][ks][1] = pack_bf2(v[2] - h[2], v[3] - h[3]);
        }
    }
    float2 bias[2];
#pragma unroll
    for (int n2 = 0; n2 < 2; ++n2) {
        const int col = wid * 16 + n2 * 8 + (lane & 3) * 2;
        bias[n2] = make_float2(b_c[col], b_c[col + 1]);
    }

    const float2* xn2 = reinterpret_cast<const float2*>(x_nodes);
    const float2* xi2 = reinterpret_cast<const float2*>(g_xint);
    const int ntiles = (NNODES + CNB - 1) / CNB;

    for (int tile = blockIdx.x; tile < ntiles; tile += gridDim.x) {
        const int n0 = tile * CNB;

        for (int idx = t; idx < CNB * 128; idx += 256) {
            const int row = idx >> 7, p = idx & 127;
            const int n = n0 + row;
            float2 v = make_float2(0.f, 0.f);
            if (n < NNODES)
                v = (p < 64) ? xn2[(size_t)n * 64 + p]
                             : xi2[(size_t)n * 64 + (p - 64)];
            const float hx = __bfloat162float(__float2bfloat16_rn(v.x));
            const float hy = __bfloat162float(__float2bfloat16_rn(v.y));
            const uint32_t off = (uint32_t)(p >> 5) * CCHUNK_B +
                swz128((uint32_t)(row * 128 + (p & 31) * 4));
            *reinterpret_cast<uint32_t*>(smem + CA_HI + off) = pack_bf2(hx, hy);
            *reinterpret_cast<uint32_t*>(smem + CA_LO + off) =
                pack_bf2(v.x - hx, v.y - hy);
        }
        __syncthreads();

        const int rowm = lane & 15;
        const int khb  = (lane >> 4) ? 16 : 0;
#pragma unroll 1
        for (int mb = 0; mb < 4; ++mb) {
            float D[2][4] = {{0.f, 0.f, 0.f, 0.f}, {0.f, 0.f, 0.f, 0.f}};
            const uint32_t rowbase = (uint32_t)((mb * 16 + rowm) * 128) + khb;
#pragma unroll
            for (int ks = 0; ks < 16; ++ks) {
                const uint32_t off = (uint32_t)(ks >> 2) * CCHUNK_B +
                    swz128(rowbase + (ks & 3) * 32);
                uint32_t Ah[4], Al[4];
                ldmatrix4(Ah, sb + CA_HI + off);
                ldmatrix4(Al, sb + CA_LO + off);
#pragma unroll
                for (int n2 = 0; n2 < 2; ++n2) {
                    mma_bf16(D[n2], Ah, Bh[n2][ks]);
                    mma_bf16(D[n2], Ah, Bl[n2][ks]);
                    mma_bf16(D[n2], Al, Bh[n2][ks]);
                }
            }
            const int g = lane >> 2, tq = lane & 3;
            const int r0 = n0 + mb * 16 + g;
#pragma unroll
            for (int n2 = 0; n2 < 2; ++n2) {
                const int col = wid * 16 + n2 * 8 + tq * 2;
                if (r0 < NNODES)
                    *reinterpret_cast<float2*>(out + (size_t)r0 * DDIM + col) =
                        make_float2(D[n2][0] + bias[n2].x, D[n2][1] + bias[n2].y);
                if (r0 + 8 < NNODES)
                    *reinterpret_cast<float2*>(out + (size_t)(r0 + 8) * DDIM + col) =
                        make_float2(D[n2][2] + bias[n2].x, D[n2][3] + bias[n2].y);
            }
        }
        __syncthreads();
    }
}

// ---------------------------------------------------------------------------
// Launch. Inputs (metadata order):
//  0 node_type(i32)  1 x_nodes(f32)  2 src(i32)  3 dst(i32)  4 rbf_edges(f32)
//  5 dist(f32)       6 emb(f32)      7 W_e(f32)  8 b_e(f32)  9 W_c(f32) 10 b_c(f32)
// ---------------------------------------------------------------------------
extern "C" void kernel_launch(void* const* d_in, const int* in_sizes, int n_in,
                              void* d_out, int out_size) {
    const int*   node_type = (const int*)  d_in[0];
    const float* x_nodes   = (const float*)d_in[1];
    const int*   src       = (const int*)  d_in[2];
    const int*   dst       = (const int*)  d_in[3];
    const float* rbf       = (const float*)d_in[4];
    const float* dist      = (const float*)d_in[5];
    const float* emb       = (const float*)d_in[6];
    const float* W_e       = (const float*)d_in[7];
    const float* b_e       = (const float*)d_in[8];
    const float* W_c       = (const float*)d_in[9];
    const float* b_c       = (const float*)d_in[10];
    float* out = (float*)d_out;

    int sms = 148;
    cudaDeviceGetAttribute(&sms, cudaDevAttrMultiProcessorCount, 0);

    cudaFuncSetAttribute(fused_edge_kernel,
                         cudaFuncAttributeMaxDynamicSharedMemorySize, EDGE_SMEM);
    cudaFuncSetAttribute(combine_mma_kernel,
                         cudaFuncAttributeMaxDynamicSharedMemorySize, COMBINE_SMEM);

    const int eb = (NEDGES + 511) / 512;  // 1172

    zero_kernel<<<2048, 256>>>();
    hist_kernel<<<eb, 512>>>(dst);
    scan_s1<<<NBLK, 256>>>();
    scan_s2<<<1, 256>>>();
    scan_s3<<<NBLK, 256>>>();
    scatter_sort_kernel<<<eb, 512>>>(dst, src, node_type, dist);
    fused_edge_kernel<<<3 * sms, 256, EDGE_SMEM>>>(rbf, emb, W_e, b_e);
    combine_mma_kernel<<<sms, 256, COMBINE_SMEM>>>(x_nodes, W_c, b_c, out);
}

// round 17
// speedup vs baseline: 1.6833x; 1.2279x over previous
#include <cuda_runtime.h>
#include <cuda_bf16.h>
#include <cuda_fp16.h>
#include <cstdint>

#define NNODES 50000
#define NEDGES 600000
#define NRBF   50
#define DDIM   128
#define CUTOFF_F 5.0f
#define PI_F 3.14159265358979f
#define NBLK   196   // ceil(50000/256)

// __device__ scratch (no cudaMalloc allowed)
__device__ float g_xint[NNODES * DDIM];    // 25.6 MB segment-sum result
__device__ int   g_count[NNODES];
__device__ int   g_cursor[NNODES];
__device__ int4  g_sedge[NEDGES];          // sorted-by-dst: {eid, dst, nt, cut_bits}
__device__ int   g_bsum[256];

// ---------------------------------------------------------------------------
__device__ __forceinline__ uint32_t smem_u32(const void* p) {
    uint32_t a;
    asm("{ .reg .u64 t; cvta.to.shared.u64 t, %1; cvt.u32.u64 %0, t; }"
        : "=r"(a) : "l"(p));
    return a;
}
__device__ __forceinline__ uint32_t swz128(uint32_t o) { return o ^ ((o >> 3) & 0x70); }

__device__ __forceinline__ void ldmatrix4(uint32_t r[4], uint32_t addr) {
    asm volatile("ldmatrix.sync.aligned.m8n8.x4.shared.b16 {%0,%1,%2,%3}, [%4];"
                 : "=r"(r[0]), "=r"(r[1]), "=r"(r[2]), "=r"(r[3]) : "r"(addr));
}
__device__ __forceinline__ void mma_bf16(float d[4], const uint32_t a[4],
                                         const uint32_t b[2]) {
    asm volatile("mma.sync.aligned.m16n8k16.row.col.f32.bf16.bf16.f32 "
                 "{%0,%1,%2,%3}, {%4,%5,%6,%7}, {%8,%9}, {%0,%1,%2,%3};"
                 : "+f"(d[0]), "+f"(d[1]), "+f"(d[2]), "+f"(d[3])
                 : "r"(a[0]), "r"(a[1]), "r"(a[2]), "r"(a[3]),
                   "r"(b[0]), "r"(b[1]));
}
__device__ __forceinline__ void mma_f16(float d[4], const uint32_t a[4],
                                        const uint32_t b[2]) {
    asm volatile("mma.sync.aligned.m16n8k16.row.col.f32.f16.f16.f32 "
                 "{%0,%1,%2,%3}, {%4,%5,%6,%7}, {%8,%9}, {%0,%1,%2,%3};"
                 : "+f"(d[0]), "+f"(d[1]), "+f"(d[2]), "+f"(d[3])
                 : "r"(a[0]), "r"(a[1]), "r"(a[2]), "r"(a[3]),
                   "r"(b[0]), "r"(b[1]));
}
__device__ __forceinline__ uint32_t pack_bf2(float x, float y) {
    __nv_bfloat162 h = __floats2bfloat162_rn(x, y);
    return *reinterpret_cast<uint32_t*>(&h);
}
__device__ __forceinline__ uint32_t pack_h2(float x, float y) {
    __half2 h = __floats2half2_rn(x, y);
    return *reinterpret_cast<uint32_t*>(&h);
}

// ---------------------------------------------------------------------------
// Zero scratch: g_xint + g_count
// ---------------------------------------------------------------------------
__global__ void zero_kernel() {
    int i = blockIdx.x * blockDim.x + threadIdx.x;
    const int n4 = NNODES * DDIM / 4;
    float4* p = reinterpret_cast<float4*>(g_xint);
    float4 z = make_float4(0.f, 0.f, 0.f, 0.f);
    for (int j = i; j < n4; j += gridDim.x * blockDim.x) p[j] = z;
    for (int j = i; j < NNODES; j += gridDim.x * blockDim.x) g_count[j] = 0;
}

// ---------------------------------------------------------------------------
// Sort chain: histogram -> 2-step scan -> scatter sorted records
// ---------------------------------------------------------------------------
__global__ void hist_kernel(const int* __restrict__ dst) {
    int e = blockIdx.x * blockDim.x + threadIdx.x;
    if (e < NEDGES) atomicAdd(&g_count[dst[e]], 1);
}

__global__ void scan_s1() {
    __shared__ int sd[256];
    const int b = blockIdx.x, t = threadIdx.x;
    const int i = b * 256 + t;
    sd[t] = (i < NNODES) ? g_count[i] : 0;
    __syncthreads();
    for (int s = 128; s > 0; s >>= 1) {
        if (t < s) sd[t] += sd[t + s];
        __syncthreads();
    }
    if (t == 0) g_bsum[b] = sd[0];
}

// merged: each block reduces its own bsum prefix (<=196 ints), then local scan
__global__ void scan_s2() {
    __shared__ int red[256];
    __shared__ int sc[256];
    const int b = blockIdx.x, t = threadIdx.x;
    int part = 0;
    for (int i = t; i < b; i += 256) part += g_bsum[i];
    red[t] = part;
    __syncthreads();
    for (int s = 128; s > 0; s >>= 1) {
        if (t < s) red[t] += red[t + s];
        __syncthreads();
    }
    const int base = red[0];
    const int i = b * 256 + t;
    const int v = (i < NNODES) ? g_count[i] : 0;
    sc[t] = v;
    __syncthreads();
    for (int off = 1; off < 256; off <<= 1) {
        int y = (t >= off) ? sc[t - off] : 0;
        __syncthreads();
        sc[t] += y;
        __syncthreads();
    }
    if (i < NNODES) g_cursor[i] = base + sc[t] - v;
}

__global__ void scatter_sort_kernel(const int* __restrict__ dst,
                                    const int* __restrict__ src,
                                    const int* __restrict__ node_type,
                                    const float* __restrict__ dist) {
    int e = blockIdx.x * blockDim.x + threadIdx.x;
    if (e < NEDGES) {
        const int d = dst[e];
        const float dis = dist[e];           // sequential read here
        float cut = 0.f;
        if (dis < CUTOFF_F)
            cut = 0.5f * (__cosf(dis * (PI_F / CUTOFF_F)) + 1.0f);
        const int idx = atomicAdd(&g_cursor[d], 1);
        g_sedge[idx] = make_int4(e, d, node_type[src[e]], __float_as_int(cut));
    }
}

// ---------------------------------------------------------------------------
// Fused edge kernel: fp16 single-pass GEMM over sorted edges + segmented
// reduction + per-segment red.global.add.v4. msg in fp16 smem.
// A: [128 rows x 64 cols] fp16 SW128 (cols 0..49 rbf, 50 = 1.0 bias, rest 0).
// ~54 KB smem -> 4 CTAs/SM.
// ---------------------------------------------------------------------------
#define TILE_E 128
#define MSGU   68                        // uint32 stride per msg row
#define A_OFF    0                                    // 16384 bytes
#define MSG_OFF  16384                                // 128*68*4 = 34816
#define CUT_OFF  (MSG_OFF + TILE_E * MSGU * 4)        // 51200
#define DST_OFF  (CUT_OFF + 512)
#define NTS_OFF  (DST_OFF + 512)
#define EID_OFF  (NTS_OFF + 512)
#define SEG_OFF  (EID_OFF + 512)
#define WTOT_OFF (SEG_OFF + 512)
#define EDGE_SMEM (WTOT_OFF + 64)                     // 53824

__device__ __forceinline__ float we_elem(const float* W_e, const float* b_e,
                                         int d, int k) {
    if (k < NRBF) return W_e[d * NRBF + k];
    if (k == NRBF) return b_e[d];
    return 0.f;
}

__global__ __launch_bounds__(256, 4) void fused_edge_kernel(
    const float* __restrict__ rbf,
    const float* __restrict__ emb,
    const float* __restrict__ W_e,
    const float* __restrict__ b_e)
{
    extern __shared__ __align__(1024) char smem[];
    const uint32_t sb = smem_u32(smem);
    const int t    = threadIdx.x;
    const int lane = t & 31;
    const int wid  = t >> 5;

    uint32_t* msg_s = reinterpret_cast<uint32_t*>(smem + MSG_OFF);
    float*    cut_s = reinterpret_cast<float*>(smem + CUT_OFF);
    int*      dst_s = reinterpret_cast<int*>(smem + DST_OFF);
    int*      nts_s = reinterpret_cast<int*>(smem + NTS_OFF);
    int*      eid_s = reinterpret_cast<int*>(smem + EID_OFF);
    int*      seg_s = reinterpret_cast<int*>(smem + SEG_OFF);
    int*      wtot_s = reinterpret_cast<int*>(smem + WTOT_OFF);

    // Zero A tile (cols >= 51 stay zero forever)
    {
        uint4* z4 = reinterpret_cast<uint4*>(smem);
        uint4 z = make_uint4(0, 0, 0, 0);
        for (int i = t; i < 16384 / 16; i += 256) z4[i] = z;
    }
    __syncthreads();
    // A col 50 = 1.0 (bias lane), constant across tiles
    if (t < TILE_E) {
        *reinterpret_cast<uint32_t*>(smem + A_OFF +
            swz128((uint32_t)(t * 128 + 100))) = pack_h2(1.0f, 0.0f);
    }

    // B = W_e fp16 fragments in registers (single precision level)
    uint32_t Bf[2][4][2];
#pragma unroll
    for (int n2 = 0; n2 < 2; ++n2) {
        const int d = wid * 16 + n2 * 8 + (lane >> 2);
#pragma unroll
        for (int ks = 0; ks < 4; ++ks) {
            const int k0 = ks * 16 + (lane & 3) * 2;
            Bf[n2][ks][0] = pack_h2(we_elem(W_e, b_e, d, k0),
                                    we_elem(W_e, b_e, d, k0 + 1));
            Bf[n2][ks][1] = pack_h2(we_elem(W_e, b_e, d, k0 + 8),
                                    we_elem(W_e, b_e, d, k0 + 9));
        }
    }
    __syncthreads();

    const int ntiles = (NEDGES + TILE_E - 1) / TILE_E;  // 4688
    const float4* emb4 = reinterpret_cast<const float4*>(emb);

    for (int tile = blockIdx.x; tile < ntiles; tile += gridDim.x) {
        const int i0 = tile * TILE_E;

        // ---- stage sorted records (cut precomputed) ----
        if (t < TILE_E) {
            const int i = i0 + t;
            int e = -1, d = -1, nt = 0;
            float cut = 0.f;
            if (i < NEDGES) {
                const int4 v = g_sedge[i];
                e = v.x; d = v.y; nt = v.z; cut = __int_as_float(v.w);
            }
            eid_s[t] = e; dst_s[t] = d; nts_s[t] = nt; cut_s[t] = cut;
        }
        __syncthreads();

        // ---- stage A tile: gathered rbf rows -> fp16, swizzled ----
        for (int idx = t; idx < TILE_E * 25; idx += 256) {
            const int row = idx / 25, p = idx - row * 25;
            const int e = eid_s[row];
            float2 v = make_float2(0.f, 0.f);
            if (e >= 0)
                v = reinterpret_cast<const float2*>(rbf + (size_t)e * NRBF)[p];
            *reinterpret_cast<uint32_t*>(smem + A_OFF +
                swz128((uint32_t)(row * 128 + p * 4))) = pack_h2(v.x, v.y);
        }
        __syncthreads();

        // ---- MMA: 8 m-blocks of 16 edges, single fp16 pass (4 ksteps) ----
        const int rowm = lane & 15;
        const int khb  = (lane >> 4) ? 16 : 0;
#pragma unroll 1
        for (int mb = 0; mb < 8; ++mb) {
            float D[2][4] = {{0.f, 0.f, 0.f, 0.f}, {0.f, 0.f, 0.f, 0.f}};
            const uint32_t rowbase = (uint32_t)((mb * 16 + rowm) * 128) + khb;
#pragma unroll
            for (int ks = 0; ks < 4; ++ks) {
                uint32_t Af[4];
                ldmatrix4(Af, sb + A_OFF + swz128(rowbase + ks * 32));
                mma_f16(D[0], Af, Bf[0][ks]);
                mma_f16(D[1], Af, Bf[1][ks]);
            }
            // fp16 msg write (stride 68 uint32 -> conflict-free)
            const int g = lane >> 2, tq = lane & 3;
            const int rr = mb * 16 + g;
            const float c0 = cut_s[rr], c8 = cut_s[rr + 8];
#pragma unroll
            for (int n2 = 0; n2 < 2; ++n2) {
                const int cu = wid * 8 + n2 * 4 + tq;   // half2 column index
                msg_s[rr * MSGU + cu]       = pack_h2(D[n2][0] * c0, D[n2][1] * c0);
                msg_s[(rr + 8) * MSGU + cu] = pack_h2(D[n2][2] * c8, D[n2][3] * c8);
            }
        }

        // ---- build segments of equal dst (ballot scan over 128 rows) ----
        int flag = 0;
        if (t < TILE_E)
            flag = (t == 0) || (dst_s[t] != dst_s[t - 1]);
        const unsigned bits = __ballot_sync(0xffffffffu, flag);
        if (t < TILE_E && lane == 0) wtot_s[wid] = __popc(bits);
        __syncthreads();
        if (t < TILE_E) {
            int base = 0;
#pragma unroll
            for (int w = 0; w < 4; ++w) base += (w < wid) ? wtot_s[w] : 0;
            if (flag) {
                const unsigned le = (lane == 31) ? 0xffffffffu
                                                 : ((1u << (lane + 1)) - 1u);
                seg_s[base + __popc(bits & le) - 1] = t;
            }
        }
        __syncthreads();
        const int nseg = wtot_s[0] + wtot_s[1] + wtot_s[2] + wtot_s[3];

        // ---- segmented sum (fp16 msg) + one red.v4 per segment per lane ----
        for (int s = wid; s < nseg; s += 8) {
            const int a = seg_s[s];
            const int b = (s + 1 < nseg) ? seg_s[s + 1] : TILE_E;
            const int dv = dst_s[a];
            if (dv < 0) continue;
            float4 acc = make_float4(0.f, 0.f, 0.f, 0.f);
            for (int j = a; j < b; ++j) {
                const uint2 h = *reinterpret_cast<const uint2*>(
                    msg_s + j * MSGU + lane * 2);
                const float2 m0 = __half22float2(*reinterpret_cast<const __half2*>(&h.x));
                const float2 m1 = __half22float2(*reinterpret_cast<const __half2*>(&h.y));
                const float4 ev = emb4[(size_t)nts_s[j] * 32 + lane];
                acc.x += m0.x * ev.x;
                acc.y += m0.y * ev.y;
                acc.z += m1.x * ev.z;
                acc.w += m1.y * ev.w;
            }
            float* p = g_xint + (size_t)dv * DDIM + lane * 4;
            asm volatile("red.global.add.v4.f32 [%0], {%1, %2, %3, %4};"
                         :: "l"(p), "f"(acc.x), "f"(acc.y),
                            "f"(acc.z), "f"(acc.w) : "memory");
        }
        __syncthreads();
    }
}

// ---------------------------------------------------------------------------
// Combine via mma.sync bf16 3-pass (proven): out[64n x 128d] tile =
//   concat(x_nodes, x_int)[64 x 256] @ W_c^T + b_c.
// ---------------------------------------------------------------------------
#define CNB 64
#define CCHUNK_B 8192
#define CA_HI 0
#define CA_LO 32768
#define COMBINE_SMEM 65536

__global__ __launch_bounds__(256, 1) void combine_mma_kernel(
    const float* __restrict__ x_nodes,
    const float* __restrict__ W_c,
    const float* __restrict__ b_c,
    float* __restrict__ out)
{
    extern __shared__ __align__(1024) char smem[];
    const uint32_t sb = smem_u32(smem);
    const int t    = threadIdx.x;
    const int lane = t & 31;
    const int wid  = t >> 5;

    uint32_t Bh[2][16][2], Bl[2][16][2];
#pragma unroll
    for (int n2 = 0; n2 < 2; ++n2) {
        const int d = wid * 16 + n2 * 8 + (lane >> 2);
#pragma unroll
        for (int ks = 0; ks < 16; ++ks) {
            const int k0 = ks * 16 + (lane & 3) * 2;
            float v[4];
            v[0] = W_c[d * 256 + k0];
            v[1] = W_c[d * 256 + k0 + 1];
            v[2] = W_c[d * 256 + k0 + 8];
            v[3] = W_c[d * 256 + k0 + 9];
            float h[4];
#pragma unroll
            for (int i = 0; i < 4; ++i)
                h[i] = __bfloat162float(__float2bfloat16_rn(v[i]));
            Bh[n2][ks][0] = pack_bf2(h[0], h[1]);
            Bh[n2][ks][1] = pack_bf2(h[2], h[3]);
            Bl[n2][ks][0] = pack_bf2(v[0] - h[0], v[1] - h[1]);
            Bl[n2][ks][1] = pack_bf2(v[2] - h[2], v[3] - h[3]);
        }
    }
    float2 bias[2];
#pragma unroll
    for (int n2 = 0; n2 < 2; ++n2) {
        const int col = wid * 16 + n2 * 8 + (lane & 3) * 2;
        bias[n2] = make_float2(b_c[col], b_c[col + 1]);
    }

    const float2* xn2 = reinterpret_cast<const float2*>(x_nodes);
    const float2* xi2 = reinterpret_cast<const float2*>(g_xint);
    const int ntiles = (NNODES + CNB - 1) / CNB;

    for (int tile = blockIdx.x; tile < ntiles; tile += gridDim.x) {
        const int n0 = tile * CNB;

        for (int idx = t; idx < CNB * 128; idx += 256) {
            const int row = idx >> 7, p = idx & 127;
            const int n = n0 + row;
            float2 v = make_float2(0.f, 0.f);
            if (n < NNODES)
                v = (p < 64) ? xn2[(size_t)n * 64 + p]
                             : xi2[(size_t)n * 64 + (p - 64)];
            const float hx = __bfloat162float(__float2bfloat16_rn(v.x));
            const float hy = __bfloat162float(__float2bfloat16_rn(v.y));
            const uint32_t off = (uint32_t)(p >> 5) * CCHUNK_B +
                swz128((uint32_t)(row * 128 + (p & 31) * 4));
            *reinterpret_cast<uint32_t*>(smem + CA_HI + off) = pack_bf2(hx, hy);
            *reinterpret_cast<uint32_t*>(smem + CA_LO + off) =
                pack_bf2(v.x - hx, v.y - hy);
        }
        __syncthreads();

        const int rowm = lane & 15;
        const int khb  = (lane >> 4) ? 16 : 0;
#pragma unroll 1
        for (int mb = 0; mb < 4; ++mb) {
            float D[2][4] = {{0.f, 0.f, 0.f, 0.f}, {0.f, 0.f, 0.f, 0.f}};
            const uint32_t rowbase = (uint32_t)((mb * 16 + rowm) * 128) + khb;
#pragma unroll
            for (int ks = 0; ks < 16; ++ks) {
                const uint32_t off = (uint32_t)(ks >> 2) * CCHUNK_B +
                    swz128(rowbase + (ks & 3) * 32);
                uint32_t Ah[4], Al[4];
                ldmatrix4(Ah, sb + CA_HI + off);
                ldmatrix4(Al, sb + CA_LO + off);
#pragma unroll
                for (int n2 = 0; n2 < 2; ++n2) {
                    mma_bf16(D[n2], Ah, Bh[n2][ks]);
                    mma_bf16(D[n2], Ah, Bl[n2][ks]);
                    mma_bf16(D[n2], Al, Bh[n2][ks]);
                }
            }
            const int g = lane >> 2, tq = lane & 3;
            const int r0 = n0 + mb * 16 + g;
#pragma unroll
            for (int n2 = 0; n2 < 2; ++n2) {
                const int col = wid * 16 + n2 * 8 + tq * 2;
                if (r0 < NNODES)
                    *reinterpret_cast<float2*>(out + (size_t)r0 * DDIM + col) =
                        make_float2(D[n2][0] + bias[n2].x, D[n2][1] + bias[n2].y);
                if (r0 + 8 < NNODES)
                    *reinterpret_cast<float2*>(out + (size_t)(r0 + 8) * DDIM + col) =
                        make_float2(D[n2][2] + bias[n2].x, D[n2][3] + bias[n2].y);
            }
        }
        __syncthreads();
    }
}

// ---------------------------------------------------------------------------
// Launch. Inputs (metadata order):
//  0 node_type(i32)  1 x_nodes(f32)  2 src(i32)  3 dst(i32)  4 rbf_edges(f32)
//  5 dist(f32)       6 emb(f32)      7 W_e(f32)  8 b_e(f32)  9 W_c(f32) 10 b_c(f32)
// ---------------------------------------------------------------------------
extern "C" void kernel_launch(void* const* d_in, const int* in_sizes, int n_in,
                              void* d_out, int out_size) {
    const int*   node_type = (const int*)  d_in[0];
    const float* x_nodes   = (const float*)d_in[1];
    const int*   src       = (const int*)  d_in[2];
    const int*   dst       = (const int*)  d_in[3];
    const float* rbf       = (const float*)d_in[4];
    const float* dist      = (const float*)d_in[5];
    const float* emb       = (const float*)d_in[6];
    const float* W_e       = (const float*)d_in[7];
    const float* b_e       = (const float*)d_in[8];
    const float* W_c       = (const float*)d_in[9];
    const float* b_c       = (const float*)d_in[10];
    float* out = (float*)d_out;

    int sms = 148;
    cudaDeviceGetAttribute(&sms, cudaDevAttrMultiProcessorCount, 0);

    cudaFuncSetAttribute(fused_edge_kernel,
                         cudaFuncAttributeMaxDynamicSharedMemorySize, EDGE_SMEM);
    cudaFuncSetAttribute(combine_mma_kernel,
                         cudaFuncAttributeMaxDynamicSharedMemorySize, COMBINE_SMEM);

    const int eb = (NEDGES + 511) / 512;  // 1172

    zero_kernel<<<2048, 256>>>();
    hist_kernel<<<eb, 512>>>(dst);
    scan_s1<<<NBLK, 256>>>();
    scan_s2<<<NBLK, 256>>>();
    scatter_sort_kernel<<<eb, 512>>>(dst, src, node_type, dist);
    fused_edge_kernel<<<4 * sms, 256, EDGE_SMEM>>>(rbf, emb, W_e, b_e);
    combine_mma_kernel<<<sms, 256, COMBINE_SMEM>>>(x_nodes, W_c, b_c, out);
}